// round 4
// baseline (speedup 1.0000x reference)
#include <cuda_runtime.h>
#include <cstdint>

#define BB 64
#define HH 1024
#define WW 1024
#define NN 256
#define MAX_ITERS 20
#define W9 (1.0f/9.0f)

#define TR   21            // tile is 21x21 raw values (radius 10)
#define TPCH 23            // smem pitch
#define TELEM (TR * TR)    // 441

// scratch
__device__ int g_end[BB * NN * 2];   // end coords after gravity (x,y)
__device__ int g_meta[BB * NN];      // winner | leader<<8 | has<<16

// ---------------------------------------------------------------------------
// Kernel 1: gravity_move, one warp per point. One 21x21 tile load supports the
// whole climb while the point stays within +-6 of the tile center (covers the
// vast majority of trajectories in one global round trip).
// ---------------------------------------------------------------------------
__global__ void __launch_bounds__(256) gravity_kernel(
    const float* __restrict__ depth, const int* __restrict__ points)
{
    const int w    = threadIdx.x >> 5;
    const int lane = threadIdx.x & 31;
    const int pidx = blockIdx.x * 8 + w;          // grid = B*N/8
    const int b    = pidx >> 8;                   // N = 256
    const float* dep = depth + (size_t)b * HH * WW;

    int px = points[pidx * 2 + 0];
    int py = points[pidx * 2 + 1];

    __shared__ float tile[8][TR * TPCH + 1];
    float* T = &tile[w][0];

    // per-lane candidate constants (cells 0..48, cell 24 = no-move)
    const int cA  = lane;
    const int rA  = cA / 7;
    const int dyA = rA - 3,  dxA = cA - rA * 7 - 3;
    const int cB  = lane + 32;
    const int rB  = cB / 7;
    const int dyB = rB - 3,  dxB = cB - rB * 7 - 3;
    const bool hasB = (cB < 49);
    // top-left of candidate 3x3 window relative to (pos - center) offset
    const int sA = (dyA + 9) * TPCH + (dxA + 9);
    const int sB = (dyB + 9) * TPCH + (dxB + 9);

    int it = 0;
    bool done = false;

    while (!done) {
        const int cy = py, cx = px;                     // tile center
        const bool guarded = (cx < 10) | (cx > WW - 11) |
                             (cy < 10) | (cy > HH - 11);   // warp-uniform

        __syncwarp();                                   // WAR vs prior reads
        if (!guarded) {
            const float* base = dep + (cy - 10) * WW + (cx - 10);
            #pragma unroll
            for (int k = 0; k < 14; ++k) {
                int e = lane + 32 * k;
                if (k < 13 || e < TELEM) {
                    int r = e / TR, c = e - r * TR;
                    T[r * TPCH + c] = __ldg(base + r * WW + c);
                }
            }
        } else {
            #pragma unroll
            for (int k = 0; k < 14; ++k) {
                int e = lane + 32 * k;
                if (k < 13 || e < TELEM) {
                    int r = e / TR, c = e - r * TR;
                    int gy = cy - 10 + r, gx = cx - 10 + c;
                    float v = 0.0f;
                    if (gy >= 0 && gy < HH && gx >= 0 && gx < WW)
                        v = __ldg(dep + gy * WW + gx);
                    T[r * TPCH + c] = v;
                }
            }
        }
        __syncwarp();

        // ---- iterate inside the tile while |pos-center|inf <= 6 ----
        while (true) {
            unsigned uA, uB = 0u;

            if (!guarded) {
                const int off = (py - cy) * TPCH + (px - cx);
                const float* p = T + off + sA;
                float a = 0.0f;
                #pragma unroll
                for (int i2 = 0; i2 < 3; ++i2)
                    #pragma unroll
                    for (int j2 = 0; j2 < 3; ++j2)
                        a = fmaf(p[i2 * TPCH + j2], W9, a);
                unsigned ua = __float_as_uint(a);
                uA = ((int)ua >= 0) ? (ua | 0x80000000u) : ~ua;

                if (hasB) {
                    const float* q = T + off + sB;
                    float b2 = 0.0f;
                    #pragma unroll
                    for (int i2 = 0; i2 < 3; ++i2)
                        #pragma unroll
                        for (int j2 = 0; j2 < 3; ++j2)
                            b2 = fmaf(q[i2 * TPCH + j2], W9, b2);
                    unsigned ub = __float_as_uint(b2);
                    uB = ((int)ub >= 0) ? (ub | 0x80000000u) : ~ub;
                }
            } else {
                // clipped candidate coords; tile radius 10 covers all windows
                {
                    int yc = min(max(py + dyA, 0), HH - 1);
                    int xc = min(max(px + dxA, 0), WW - 1);
                    const float* p = T + (yc - cy + 9) * TPCH + (xc - cx + 9);
                    float a = 0.0f;
                    #pragma unroll
                    for (int i2 = 0; i2 < 3; ++i2)
                        #pragma unroll
                        for (int j2 = 0; j2 < 3; ++j2)
                            a = fmaf(p[i2 * TPCH + j2], W9, a);
                    unsigned ua = __float_as_uint(a);
                    uA = ((int)ua >= 0) ? (ua | 0x80000000u) : ~ua;
                }
                if (hasB) {
                    int yc = min(max(py + dyB, 0), HH - 1);
                    int xc = min(max(px + dxB, 0), WW - 1);
                    const float* q = T + (yc - cy + 9) * TPCH + (xc - cx + 9);
                    float b2 = 0.0f;
                    #pragma unroll
                    for (int i2 = 0; i2 < 3; ++i2)
                        #pragma unroll
                        for (int j2 = 0; j2 < 3; ++j2)
                            b2 = fmaf(q[i2 * TPCH + j2], W9, b2);
                    unsigned ub = __float_as_uint(b2);
                    uB = ((int)ub >= 0) ? (ub | 0x80000000u) : ~ub;
                }
            }

            // warp argmax with exact first-index tie-break:
            // A-cells are 0..31 (== lane), B-cells 32..48 (== lane+32).
            unsigned wmax = __reduce_max_sync(0xffffffffu, max(uA, uB));
            unsigned balA = __ballot_sync(0xffffffffu, uA == wmax);
            unsigned balB = __ballot_sync(0xffffffffu, uB == wmax);
            int besti = balA ? (__ffs(balA) - 1) : (__ffs(balB) + 31);

            int rr = besti / 7;
            int ny = min(max(py + rr - 3, 0), HH - 1);
            int nx = min(max(px + besti - rr * 7 - 3, 0), WW - 1);
            bool moved = (nx != px) | (ny != py);
            px = nx; py = ny; ++it;

            if (!moved || it >= MAX_ITERS) { done = true; break; }
            if (px < cx - 6 || px > cx + 6 ||
                py < cy - 6 || py > cy + 6) break;      // re-center + reload
        }
    }

    if (lane == 0) {
        g_end[pidx * 2 + 0] = px;
        g_end[pidx * 2 + 1] = py;
    }
}

// ---------------------------------------------------------------------------
// Kernel 2: pairwise overlap stats, one warp per point (lane covers 8 j's).
// ---------------------------------------------------------------------------
__global__ void __launch_bounds__(256) pairwise_kernel(
    const int* __restrict__ points)
{
    const int w    = threadIdx.x >> 5;
    const int lane = threadIdx.x & 31;
    const int blkInBatch = blockIdx.x & 31;
    const int b    = blockIdx.x >> 5;
    const int base = b * NN;

    __shared__ int ex[NN], ey[NN], sx[NN], sy[NN];
    const int t = threadIdx.x;
    ex[t] = g_end[(base + t) * 2 + 0];
    ey[t] = g_end[(base + t) * 2 + 1];
    sx[t] = points[(base + t) * 2 + 0];
    sy[t] = points[(base + t) * 2 + 1];
    __syncthreads();

    const int i   = blkInBatch * 8 + w;
    const int exi = ex[i], eyi = ey[i];

    int cnt = 0, minlead = 0x7fffffff;
    int bestd = 0x7fffffff, bestj = 0x7fffffff;

    #pragma unroll
    for (int k = 0; k < 8; ++k) {
        int j   = lane + 32 * k;
        int ddx = exi - ex[j], ddy = eyi - ey[j];
        int de  = ddx * ddx + ddy * ddy;
        if (de < 4) {                             // dist < 2.0 <=> sq < 4
            cnt++;
            minlead = min(minlead, j);            // argmax(ov) = first True
            int sdx = sx[j] - exi, sdy = sy[j] - eyi;
            int sd  = sdx * sdx + sdy * sdy;
            if (sd < bestd || (sd == bestd && j < bestj)) { bestd = sd; bestj = j; }
        }
    }

    #pragma unroll
    for (int o = 16; o; o >>= 1) {
        cnt     += __shfl_xor_sync(0xffffffffu, cnt, o);
        minlead  = min(minlead, __shfl_xor_sync(0xffffffffu, minlead, o));
        int od   = __shfl_xor_sync(0xffffffffu, bestd, o);
        int oj   = __shfl_xor_sync(0xffffffffu, bestj, o);
        if (od < bestd || (od == bestd && oj < bestj)) { bestd = od; bestj = oj; }
    }

    if (lane == 0)
        g_meta[base + i] = bestj | (minlead << 8) | ((cnt > 1) << 16);
}

// ---------------------------------------------------------------------------
// Kernel 3: finalize coordinates + peak (exact row-major 3x3 fma chain).
// ---------------------------------------------------------------------------
__global__ void __launch_bounds__(128) finalize_kernel(
    const float* __restrict__ depth, const int* __restrict__ points,
    float* __restrict__ out)
{
    const int gid  = blockIdx.x * 128 + threadIdx.x;   // 0..16383
    const int b    = gid >> 8;
    const int base = b * NN;
    const int i    = gid & 255;

    const int meta   = g_meta[gid];
    const int leader = (meta >> 8) & 0xff;
    const bool has   = (meta >> 16) & 1;
    const int wol    = g_meta[base + leader] & 0xff;   // winner[leader]

    int fx, fy;
    if (has) {
        if (i == wol) {
            fx = g_end[(base + leader) * 2 + 0];
            fy = g_end[(base + leader) * 2 + 1];
        } else {
            fx = points[gid * 2 + 0];
            fy = points[gid * 2 + 1];
        }
    } else {
        fx = g_end[gid * 2 + 0];
        fy = g_end[gid * 2 + 1];
    }

    const float* dep = depth + (size_t)b * HH * WW;
    float acc = 0.0f;
    #pragma unroll
    for (int u = -1; u <= 1; ++u)
        #pragma unroll
        for (int v = -1; v <= 1; ++v) {
            int gy = fy + u, gx = fx + v;
            float val = (gy >= 0 && gy < HH && gx >= 0 && gx < WW)
                            ? __ldg(dep + gy * WW + gx) : 0.0f;
            acc = fmaf(val, W9, acc);
        }

    out[gid * 2 + 0] = (float)fx;
    out[gid * 2 + 1] = (float)fy;
    out[BB * NN * 2 + gid] = acc;
}

// ---------------------------------------------------------------------------
extern "C" void kernel_launch(void* const* d_in, const int* in_sizes, int n_in,
                              void* d_out, int out_size)
{
    const float* depth  = (const float*)d_in[0];   // (64,1,1024,1024) f32
    const int*   points = (const int*)d_in[1];     // (64,256,2) i32
    float* out = (float*)d_out;                    // end (B,N,2) ++ peak (B,N)

    gravity_kernel <<<(BB * NN) / 8, 256>>>(depth, points);
    pairwise_kernel<<<BB * 32,       256>>>(points);
    finalize_kernel<<<(BB * NN) / 128, 128>>>(depth, points, out);
}

// round 5
// speedup vs baseline: 1.2531x; 1.2531x over previous
#include <cuda_runtime.h>
#include <cstdint>

#define BB 64
#define HH 1024
#define WW 1024
#define NN 256
#define MAX_ITERS 20
#define W9 (1.0f/9.0f)

// scratch
__device__ int g_end[BB * NN * 2];   // end coords after gravity (x,y)
__device__ int g_meta[BB * NN];      // winner | leader<<8 | has<<16

// ---------------------------------------------------------------------------
// Kernel 1: gravity_move, one warp per point, 2 warps per block (small blocks
// retire fast -> high achieved occupancy). 9x9 raw window per iteration,
// smoothing on the fly; REDUX-based argmax with exact first-index tie-break.
// ---------------------------------------------------------------------------
__global__ void __launch_bounds__(64) gravity_kernel(
    const float* __restrict__ depth, const int* __restrict__ points)
{
    const int w    = threadIdx.x >> 5;
    const int lane = threadIdx.x & 31;
    const int pidx = blockIdx.x * 2 + w;          // grid = B*N/2
    const int b    = pidx >> 8;                   // N = 256
    const float* dep = depth + (size_t)b * HH * WW;

    int px = points[pidx * 2 + 0];
    int py = points[pidx * 2 + 1];

    __shared__ float tile[2][9 * 12 + 4];         // 9x9 window, pitch 12
    float* T = &tile[w][0];

    // ---- loop-invariant per-lane constants ----
    // load slots: elements lane, lane+32, lane+64 of the 81-element tile
    const int r0 = lane / 9,        c0 = lane - r0 * 9;
    const int e1 = lane + 32;
    const int r1 = e1 / 9,          c1 = e1 - r1 * 9;
    const int e2 = lane + 64;
    const int r2 = e2 / 9,          c2 = e2 - r2 * 9;
    const bool l3 = (lane < 17);                  // e2 < 81
    const int go0 = r0 * WW + c0,   so0 = r0 * 12 + c0;
    const int go1 = r1 * WW + c1,   so1 = r1 * 12 + c1;
    const int go2 = r2 * WW + c2,   so2 = r2 * 12 + c2;

    // candidate cells: lane and lane+32 (cells 0..48)
    const int cA  = lane;
    const int rA  = cA / 7;
    const int dyA = rA - 3,  dxA = cA - rA * 7 - 3;
    const int cB  = lane + 32;
    const int rB  = cB / 7;
    const int dyB = rB - 3,  dxB = cB - rB * 7 - 3;
    const bool hasB = (cB < 49);
    const int sAo = (dyA + 3) * 12 + (dxA + 3);   // top-left of 3x3 in tile
    const int sBo = (dyB + 3) * 12 + (dxB + 3);

    for (int it = 0; it < MAX_ITERS; ++it) {
        const int by = py - 4, bx = px - 4;
        const bool interior = (px >= 4) & (px <= WW - 5) &
                              (py >= 4) & (py <= HH - 5);   // warp-uniform

        if (interior) {
            const float* base = dep + by * WW + bx;
            T[so0] = __ldg(base + go0);
            T[so1] = __ldg(base + go1);
            if (l3) T[so2] = __ldg(base + go2);
        } else {
            {
                int gy = by + r0, gx = bx + c0;
                T[so0] = (gy >= 0 && gy < HH && gx >= 0 && gx < WW)
                             ? __ldg(dep + gy * WW + gx) : 0.0f;
            }
            {
                int gy = by + r1, gx = bx + c1;
                T[so1] = (gy >= 0 && gy < HH && gx >= 0 && gx < WW)
                             ? __ldg(dep + gy * WW + gx) : 0.0f;
            }
            if (l3) {
                int gy = by + r2, gx = bx + c2;
                T[so2] = (gy >= 0 && gy < HH && gx >= 0 && gx < WW)
                             ? __ldg(dep + gy * WW + gx) : 0.0f;
            }
        }
        __syncwarp();

        unsigned uA, uB = 0u;
        if (interior) {
            const float* p = T + sAo;
            float a = 0.0f;
            #pragma unroll
            for (int i2 = 0; i2 < 3; ++i2)
                #pragma unroll
                for (int j2 = 0; j2 < 3; ++j2)
                    a = fmaf(p[i2 * 12 + j2], W9, a);
            unsigned ua = __float_as_uint(a);
            uA = ((int)ua >= 0) ? (ua | 0x80000000u) : ~ua;

            if (hasB) {
                const float* q = T + sBo;
                float b2 = 0.0f;
                #pragma unroll
                for (int i2 = 0; i2 < 3; ++i2)
                    #pragma unroll
                    for (int j2 = 0; j2 < 3; ++j2)
                        b2 = fmaf(q[i2 * 12 + j2], W9, b2);
                unsigned ub = __float_as_uint(b2);
                uB = ((int)ub >= 0) ? (ub | 0x80000000u) : ~ub;
            }
        } else {
            // border path: clipped candidate coords (exact dup ties resolved
            // by first-index tie-break below)
            {
                int yc = min(max(py + dyA, 0), HH - 1);
                int xc = min(max(px + dxA, 0), WW - 1);
                const float* p = T + (yc - by - 1) * 12 + (xc - bx - 1);
                float a = 0.0f;
                #pragma unroll
                for (int i2 = 0; i2 < 3; ++i2)
                    #pragma unroll
                    for (int j2 = 0; j2 < 3; ++j2)
                        a = fmaf(p[i2 * 12 + j2], W9, a);
                unsigned ua = __float_as_uint(a);
                uA = ((int)ua >= 0) ? (ua | 0x80000000u) : ~ua;
            }
            if (hasB) {
                int yc = min(max(py + dyB, 0), HH - 1);
                int xc = min(max(px + dxB, 0), WW - 1);
                const float* q = T + (yc - by - 1) * 12 + (xc - bx - 1);
                float b2 = 0.0f;
                #pragma unroll
                for (int i2 = 0; i2 < 3; ++i2)
                    #pragma unroll
                    for (int j2 = 0; j2 < 3; ++j2)
                        b2 = fmaf(q[i2 * 12 + j2], W9, b2);
                unsigned ub = __float_as_uint(b2);
                uB = ((int)ub >= 0) ? (ub | 0x80000000u) : ~ub;
            }
        }

        // warp argmax, exact first-index tie-break:
        // A-cells are 0..31 (== lane), B-cells 32..48 (== lane+32).
        unsigned wmax = __reduce_max_sync(0xffffffffu, max(uA, uB));
        unsigned balA = __ballot_sync(0xffffffffu, uA == wmax);
        unsigned balB = __ballot_sync(0xffffffffu, uB == wmax);
        int besti = balA ? (__ffs(balA) - 1) : (__ffs(balB) + 31);

        int rr = besti / 7;
        int ny = min(max(py + rr - 3, 0), HH - 1);
        int nx = min(max(px + besti - rr * 7 - 3, 0), WW - 1);
        bool moved = (nx != px) | (ny != py);
        px = nx; py = ny;
        __syncwarp();
        if (!moved) break;                        // fixed point stays fixed
    }

    if (lane == 0) {
        g_end[pidx * 2 + 0] = px;
        g_end[pidx * 2 + 1] = py;
    }
}

// ---------------------------------------------------------------------------
// Kernel 2: pairwise overlap stats, one warp per point (lane covers 8 j's).
// ---------------------------------------------------------------------------
__global__ void __launch_bounds__(256) pairwise_kernel(
    const int* __restrict__ points)
{
    const int w    = threadIdx.x >> 5;
    const int lane = threadIdx.x & 31;
    const int blkInBatch = blockIdx.x & 31;
    const int b    = blockIdx.x >> 5;
    const int base = b * NN;

    __shared__ int ex[NN], ey[NN], sx[NN], sy[NN];
    const int t = threadIdx.x;
    ex[t] = g_end[(base + t) * 2 + 0];
    ey[t] = g_end[(base + t) * 2 + 1];
    sx[t] = points[(base + t) * 2 + 0];
    sy[t] = points[(base + t) * 2 + 1];
    __syncthreads();

    const int i   = blkInBatch * 8 + w;
    const int exi = ex[i], eyi = ey[i];

    int cnt = 0, minlead = 0x7fffffff;
    int bestd = 0x7fffffff, bestj = 0x7fffffff;

    #pragma unroll
    for (int k = 0; k < 8; ++k) {
        int j   = lane + 32 * k;
        int ddx = exi - ex[j], ddy = eyi - ey[j];
        int de  = ddx * ddx + ddy * ddy;
        if (de < 4) {                             // dist < 2.0 <=> sq < 4
            cnt++;
            minlead = min(minlead, j);            // argmax(ov) = first True
            int sdx = sx[j] - exi, sdy = sy[j] - eyi;
            int sd  = sdx * sdx + sdy * sdy;
            if (sd < bestd || (sd == bestd && j < bestj)) { bestd = sd; bestj = j; }
        }
    }

    #pragma unroll
    for (int o = 16; o; o >>= 1) {
        cnt     += __shfl_xor_sync(0xffffffffu, cnt, o);
        minlead  = min(minlead, __shfl_xor_sync(0xffffffffu, minlead, o));
        int od   = __shfl_xor_sync(0xffffffffu, bestd, o);
        int oj   = __shfl_xor_sync(0xffffffffu, bestj, o);
        if (od < bestd || (od == bestd && oj < bestj)) { bestd = od; bestj = oj; }
    }

    if (lane == 0)
        g_meta[base + i] = bestj | (minlead << 8) | ((cnt > 1) << 16);
}

// ---------------------------------------------------------------------------
// Kernel 3: finalize coordinates + peak (exact row-major 3x3 fma chain).
// ---------------------------------------------------------------------------
__global__ void __launch_bounds__(128) finalize_kernel(
    const float* __restrict__ depth, const int* __restrict__ points,
    float* __restrict__ out)
{
    const int gid  = blockIdx.x * 128 + threadIdx.x;   // 0..16383
    const int b    = gid >> 8;
    const int base = b * NN;
    const int i    = gid & 255;

    const int meta   = g_meta[gid];
    const int leader = (meta >> 8) & 0xff;
    const bool has   = (meta >> 16) & 1;
    const int wol    = g_meta[base + leader] & 0xff;   // winner[leader]

    int fx, fy;
    if (has) {
        if (i == wol) {
            fx = g_end[(base + leader) * 2 + 0];
            fy = g_end[(base + leader) * 2 + 1];
        } else {
            fx = points[gid * 2 + 0];
            fy = points[gid * 2 + 1];
        }
    } else {
        fx = g_end[gid * 2 + 0];
        fy = g_end[gid * 2 + 1];
    }

    const float* dep = depth + (size_t)b * HH * WW;
    float acc = 0.0f;
    #pragma unroll
    for (int u = -1; u <= 1; ++u)
        #pragma unroll
        for (int v = -1; v <= 1; ++v) {
            int gy = fy + u, gx = fx + v;
            float val = (gy >= 0 && gy < HH && gx >= 0 && gx < WW)
                            ? __ldg(dep + gy * WW + gx) : 0.0f;
            acc = fmaf(val, W9, acc);
        }

    out[gid * 2 + 0] = (float)fx;
    out[gid * 2 + 1] = (float)fy;
    out[BB * NN * 2 + gid] = acc;
}

// ---------------------------------------------------------------------------
extern "C" void kernel_launch(void* const* d_in, const int* in_sizes, int n_in,
                              void* d_out, int out_size)
{
    const float* depth  = (const float*)d_in[0];   // (64,1,1024,1024) f32
    const int*   points = (const int*)d_in[1];     // (64,256,2) i32
    float* out = (float*)d_out;                    // end (B,N,2) ++ peak (B,N)

    gravity_kernel <<<(BB * NN) / 2, 64>>>(depth, points);
    pairwise_kernel<<<BB * 32,       256>>>(points);
    finalize_kernel<<<(BB * NN) / 128, 128>>>(depth, points, out);
}